// round 1
// baseline (speedup 1.0000x reference)
#include <cuda_runtime.h>
#include <cstdint>
#include <cstddef>

#define SEQ    2048
#define BATCH  128
#define INPUT  256
#define HIDDEN 512
#define MDIM   (SEQ * BATCH)          // 262144 GEMM rows

// Scratch for the two projections that can't live in d_out.
// (xh goes straight into d_out's output region and is overwritten in place by the scan.)
__device__ float g_xc[(size_t)SEQ * BATCH * HIDDEN];
__device__ float g_xa[(size_t)SEQ * BATCH * HIDDEN];

// ---------------------------------------------------------------------------
// Phase 1: three fused projections  C[m,n] = sum_k x[m,k] * U[n,k]  (+ bias)
// Tile: 128(M) x 128(N) x 8(K), 256 threads, 8x8 per thread,
// accumulation via packed fma.rn.f32x2 (2 FMA per issue slot on sm_103a).
// grid.x = 12 (proj*4 + n-block)  -> consecutive CTAs share the same A rows (L2 reuse)
// grid.y = MDIM/128 = 2048
// ---------------------------------------------------------------------------
__global__ __launch_bounds__(256, 2)
void brc_gemm3(const float* __restrict__ A,
               const float* __restrict__ Uc, const float* __restrict__ Ua,
               const float* __restrict__ Uh,
               const float* __restrict__ bc, const float* __restrict__ ba,
               float* __restrict__ xh_out)
{
    __shared__ float As[2][8][128];
    __shared__ float Bs[2][8][128];

    const int colblk = blockIdx.x;     // 0..11
    const int proj   = colblk >> 2;    // 0..2
    const int nb     = colblk & 3;     // 0..3 (column block within 512)
    const int mb     = blockIdx.y;     // 0..2047

    const float* __restrict__ B    = (proj == 0) ? Uc : (proj == 1) ? Ua : Uh;
    float*       __restrict__ C    = (proj == 0) ? g_xc : (proj == 1) ? g_xa : xh_out;
    const float* __restrict__ bias = (proj == 0) ? bc : (proj == 1) ? ba : nullptr;

    const int tid = threadIdx.x;
    const int lr  = tid >> 1;          // 0..127 : tile row to load
    const int lk  = (tid & 1) << 2;    // 0 or 4 : k sub-offset (float4)

    const float* Aptr = A + (size_t)(mb * 128 + lr) * INPUT + lk;
    const float* Bptr = B + (size_t)(nb * 128 + lr) * INPUT + lk;

    const int ty = tid >> 4;           // 0..15
    const int tx = tid & 15;           // 0..15

    unsigned long long acc[8][4];      // 8 rows x 4 f32x2 pairs = 8x8 fp32
#pragma unroll
    for (int i = 0; i < 8; i++)
#pragma unroll
        for (int p = 0; p < 4; p++) acc[i][p] = 0ull;

    // preload tile 0
    float4 aReg = *(const float4*)Aptr;
    float4 bReg = *(const float4*)Bptr;
#pragma unroll
    for (int q = 0; q < 4; q++) {
        As[0][lk + q][lr] = ((const float*)&aReg)[q];
        Bs[0][lk + q][lr] = ((const float*)&bReg)[q];
    }
    __syncthreads();

    const int NKT = INPUT / 8;   // 32 k-tiles
    for (int kt = 0; kt < NKT; ++kt) {
        const int buf = kt & 1;
        if (kt + 1 < NKT) {
            aReg = *(const float4*)(Aptr + (kt + 1) * 8);
            bReg = *(const float4*)(Bptr + (kt + 1) * 8);
        }
#pragma unroll
        for (int k = 0; k < 8; k++) {
            float  av[8];
            float2 bv[4];
            *(float4*)&av[0] = *(const float4*)&As[buf][k][ty * 8];
            *(float4*)&av[4] = *(const float4*)&As[buf][k][ty * 8 + 4];
            *(float4*)&bv[0] = *(const float4*)&Bs[buf][k][tx * 8];
            *(float4*)&bv[2] = *(const float4*)&Bs[buf][k][tx * 8 + 4];
#pragma unroll
            for (int i = 0; i < 8; i++) {
                unsigned long long a2;
                asm("mov.b64 %0, {%1, %1};" : "=l"(a2) : "f"(av[i]));
#pragma unroll
                for (int p = 0; p < 4; p++) {
                    unsigned long long b2;
                    b2 = *(unsigned long long*)&bv[p];
                    asm("fma.rn.f32x2 %0, %1, %2, %0;"
                        : "+l"(acc[i][p]) : "l"(a2), "l"(b2));
                }
            }
        }
        if (kt + 1 < NKT) {
            const int nbuf = buf ^ 1;
#pragma unroll
            for (int q = 0; q < 4; q++) {
                As[nbuf][lk + q][lr] = ((const float*)&aReg)[q];
                Bs[nbuf][lk + q][lr] = ((const float*)&bReg)[q];
            }
            __syncthreads();
        }
    }

    // epilogue: bias + store
    float bv8[8];
#pragma unroll
    for (int q = 0; q < 8; q++)
        bv8[q] = bias ? bias[nb * 128 + tx * 8 + q] : 0.0f;

#pragma unroll
    for (int i = 0; i < 8; i++) {
        const size_t row = (size_t)mb * 128 + ty * 8 + i;
        float out8[8];
#pragma unroll
        for (int p = 0; p < 4; p++) {
            float2 v = *(float2*)&acc[i][p];
            out8[2 * p]     = v.x + bv8[2 * p];
            out8[2 * p + 1] = v.y + bv8[2 * p + 1];
        }
        float* cp = C + row * HIDDEN + nb * 128 + tx * 8;
        *(float4*)cp       = *(const float4*)&out8[0];
        *(float4*)(cp + 4) = *(const float4*)&out8[4];
    }
}

// ---------------------------------------------------------------------------
// Phase 2: persistent scan. One thread per (batch, hidden) element = 65536
// threads; 2048 sequential steps with one-step prefetch of next (xc, xa, xh).
// `out` initially holds xh; each step's output h[t] overwrites out[t] in place.
// ---------------------------------------------------------------------------
__global__ __launch_bounds__(256)
void brc_scan(float* __restrict__ out,
              const float* __restrict__ h0,
              const float* __restrict__ w_c,
              const float* __restrict__ w_a,
              float* __restrict__ hn)
{
    const int tid = blockIdx.x * blockDim.x + threadIdx.x;   // 0..65535
    const int j   = tid & (HIDDEN - 1);
    const float wc = w_c[j];
    const float wa = w_a[j];
    float h = h0[tid];

    const int STRIDE = BATCH * HIDDEN;  // 65536

    // prefetch t = 0
    float xct = g_xc[tid];
    float xat = g_xa[tid];
    float xht = out[tid];

    for (int t = 0; t < SEQ; ++t) {
        const size_t idx = (size_t)t * STRIDE + tid;
        const float xc_c = xct, xa_c = xat, xh_c = xht;
        if (t + 1 < SEQ) {
            xct = g_xc[idx + STRIDE];
            xat = g_xa[idx + STRIDE];
            xht = out[idx + STRIDE];
        }
        const float c = 1.0f / (1.0f + __expf(-(xc_c + wc * h)));
        const float a = 1.0f + tanhf(xa_c + wa * h);
        h = c * h + (1.0f - c) * tanhf(xh_c + a * h);
        out[idx] = h;
    }
    if (hn) hn[tid] = h;
}

// ---------------------------------------------------------------------------
extern "C" void kernel_launch(void* const* d_in, const int* in_sizes, int n_in,
                              void* d_out, int out_size)
{
    const float* x  = (const float*)d_in[0];  // (SEQ, BATCH, INPUT)
    const float* h0 = (const float*)d_in[1];  // (BATCH, HIDDEN)
    const float* Uc = (const float*)d_in[2];  // (HIDDEN, INPUT)
    const float* wc = (const float*)d_in[3];  // (HIDDEN,)
    const float* bc = (const float*)d_in[4];  // (HIDDEN,)
    const float* Ua = (const float*)d_in[5];
    const float* wa = (const float*)d_in[6];
    const float* ba = (const float*)d_in[7];
    const float* Uh = (const float*)d_in[8];

    float* out = (float*)d_out;
    const size_t out_elems = (size_t)SEQ * BATCH * HIDDEN;
    // hn region follows the main output if the buffer includes it
    float* hn = ((size_t)out_size >= out_elems + (size_t)BATCH * HIDDEN)
                    ? (out + out_elems) : nullptr;

    // Phase 1: 3 projections (xc -> g_xc, xa -> g_xa, xh -> d_out region)
    dim3 grid(12, MDIM / 128);
    brc_gemm3<<<grid, 256>>>(x, Uc, Ua, Uh, bc, ba, out);

    // Phase 2: sequential scan, in-place over xh
    brc_scan<<<(BATCH * HIDDEN) / 256, 256>>>(out, h0, wc, wa, hn);
}

// round 3
// speedup vs baseline: 2.3922x; 2.3922x over previous
#include <cuda_runtime.h>
#include <cuda_bf16.h>
#include <cstdint>
#include <cstddef>

#define SEQ    2048
#define BATCH  128
#define INPUT  256
#define HIDDEN 512
#define MDIM   (SEQ * BATCH)          // 262144 GEMM rows

// ---------------------------------------------------------------------------
// Device scratch (no allocations allowed)
// ---------------------------------------------------------------------------
__device__ float g_xc[(size_t)SEQ * BATCH * HIDDEN];
__device__ float g_xa[(size_t)SEQ * BATCH * HIDDEN];
__device__ __nv_bfloat16 g_Ahi[(size_t)MDIM * INPUT];
__device__ __nv_bfloat16 g_Alo[(size_t)MDIM * INPUT];
__device__ __nv_bfloat16 g_Bhi[3 * HIDDEN * INPUT];
__device__ __nv_bfloat16 g_Blo[3 * HIDDEN * INPUT];

// ---------------------------------------------------------------------------
// PTX helpers (all plain sm_80-level PTX; assembles for compute_103)
// ---------------------------------------------------------------------------
__device__ __forceinline__ uint32_t smem_to_u32(const void* p) {
    uint32_t a;
    asm("{ .reg .u64 t; cvta.to.shared.u64 t, %1; cvt.u32.u64 %0, t; }"
        : "=r"(a) : "l"(p));
    return a;
}
__device__ __forceinline__ void cp16(uint32_t dst, const void* src) {
    asm volatile("cp.async.cg.shared.global [%0], [%1], 16;"
                 :: "r"(dst), "l"(src));
}
#define CP_COMMIT() asm volatile("cp.async.commit_group;" ::: "memory")
#define CP_WAIT(n)  asm volatile("cp.async.wait_group %0;" :: "n"(n) : "memory")

__device__ __forceinline__ void ldsm_x4(uint32_t* r, uint32_t addr) {
    asm volatile("ldmatrix.sync.aligned.m8n8.x4.shared.b16 {%0,%1,%2,%3}, [%4];"
                 : "=r"(r[0]), "=r"(r[1]), "=r"(r[2]), "=r"(r[3]) : "r"(addr));
}
__device__ __forceinline__ void ldsm_x2(uint32_t* r, uint32_t addr) {
    asm volatile("ldmatrix.sync.aligned.m8n8.x2.shared.b16 {%0,%1}, [%2];"
                 : "=r"(r[0]), "=r"(r[1]) : "r"(addr));
}
__device__ __forceinline__ void mma16816(float* c, const uint32_t* a,
                                         const uint32_t* b) {
    asm volatile(
        "mma.sync.aligned.m16n8k16.row.col.f32.bf16.bf16.f32 "
        "{%0,%1,%2,%3}, {%4,%5,%6,%7}, {%8,%9}, {%0,%1,%2,%3};"
        : "+f"(c[0]), "+f"(c[1]), "+f"(c[2]), "+f"(c[3])
        : "r"(a[0]), "r"(a[1]), "r"(a[2]), "r"(a[3]), "r"(b[0]), "r"(b[1]));
}

// ---------------------------------------------------------------------------
// Pre-pass: split fp32 -> bf16 hi/lo
// ---------------------------------------------------------------------------
__global__ void splitA(const float* __restrict__ x) {
    const size_t i = (size_t)blockIdx.x * blockDim.x + threadIdx.x;
    const size_t base = i * 8;
    float4 a = *(const float4*)(x + base);
    float4 b = *(const float4*)(x + base + 4);
    float f[8] = {a.x, a.y, a.z, a.w, b.x, b.y, b.z, b.w};
    union { __nv_bfloat16 h[8]; uint4 u; } H, L;
#pragma unroll
    for (int k = 0; k < 8; k++) {
        H.h[k] = __float2bfloat16_rn(f[k]);
        L.h[k] = __float2bfloat16_rn(f[k] - __bfloat162float(H.h[k]));
    }
    *(uint4*)(g_Ahi + base) = H.u;
    *(uint4*)(g_Alo + base) = L.u;
}
__global__ void splitB(const float* __restrict__ u, int proj) {
    const size_t i = (size_t)blockIdx.x * blockDim.x + threadIdx.x;
    const size_t base = i * 8;
    const size_t off = (size_t)proj * HIDDEN * INPUT;
    float4 a = *(const float4*)(u + base);
    float4 b = *(const float4*)(u + base + 4);
    float f[8] = {a.x, a.y, a.z, a.w, b.x, b.y, b.z, b.w};
    union { __nv_bfloat16 h[8]; uint4 u4; } H, L;
#pragma unroll
    for (int k = 0; k < 8; k++) {
        H.h[k] = __float2bfloat16_rn(f[k]);
        L.h[k] = __float2bfloat16_rn(f[k] - __bfloat162float(H.h[k]));
    }
    *(uint4*)(g_Bhi + off + base) = H.u4;
    *(uint4*)(g_Blo + off + base) = L.u4;
}

// ---------------------------------------------------------------------------
// mma.sync bf16 GEMM. grid = (12, 2048): x = proj*4 + nblock, y = mtile.
// CTA tile 128(M) x 128(N), K in 8 chunks of 32, cp.async double buffer.
// 8 warps as 4(M) x 2(N): warp tile 32 x 64.
// 3 split terms accumulate into one fp32 C: Ah*Bh + Al*Bh + Ah*Bl.
// SMEM: K-major rows padded to 80B -> conflict-free non-trans ldmatrix.
// ---------------------------------------------------------------------------
#define KC     32
#define NCH    (INPUT / KC)           // 8
#define ROWB   80                     // 64B data + 16B pad
#define MATB   (128 * ROWB)           // 10240 B per matrix tile
#define BUFB   (4 * MATB)             // Ah | Al | Bh | Bl = 40960 B
#define SM_BIAS (2 * BUFB)            // 81920
#define SMEM_TOT (2 * BUFB + 512)     // 82432

__global__ __launch_bounds__(256, 2)
void brc_gemm_mma(const float* __restrict__ bc, const float* __restrict__ ba,
                  float* __restrict__ xh_out) {
    extern __shared__ __align__(16) char smem[];
    const uint32_t sb = smem_to_u32(smem);
    const int tid = threadIdx.x;
    const int wid = tid >> 5;
    const int lid = tid & 31;

    const int colblk = blockIdx.x;     // 0..11
    const int proj   = colblk >> 2;
    const int nb     = colblk & 3;
    const int mb     = blockIdx.y;     // 0..2047

    float* __restrict__ C = (proj == 0) ? g_xc : (proj == 1) ? g_xa : xh_out;

    // bias -> smem (zero for proj 2)
    if (tid < 128) {
        float bv = 0.0f;
        if (proj == 0) bv = bc[nb * 128 + tid];
        else if (proj == 1) bv = ba[nb * 128 + tid];
        ((float*)(smem + SM_BIAS))[tid] = bv;
    }

    const __nv_bfloat16* __restrict__ srcs[4] = {
        g_Ahi + (size_t)mb * 128 * INPUT,
        g_Alo + (size_t)mb * 128 * INPUT,
        g_Bhi + (size_t)proj * HIDDEN * INPUT + (size_t)(nb * 128) * INPUT,
        g_Blo + (size_t)proj * HIDDEN * INPUT + (size_t)(nb * 128) * INPUT
    };

    // copy chunk c into buffer b: 2048 x 16B via cp.async (8 per thread)
    auto copy_chunk = [&](int c, int b) {
#pragma unroll
        for (int i = 0; i < 8; i++) {
            const int mat = i >> 1;                       // compile-time per i
            const int within = ((i & 1) << 8) + tid;      // 0..511
            const int r = within >> 2;
            const int s = within & 3;
            const __nv_bfloat16* g = srcs[mat] + (size_t)r * INPUT + c * KC + s * 8;
            cp16(sb + b * BUFB + mat * MATB + r * ROWB + s * 16, g);
        }
        CP_COMMIT();
    };

    // warp layout: 4(M) x 2(N)
    const int wm = wid & 3;            // M group: warp rows wm*32..wm*32+31
    const int wn = wid >> 2;           // N group: warp cols wn*64..wn*64+63

    // ldmatrix per-lane address components (element units)
    const int aRow = wm * 32 + (lid & 15);        // + mt*16
    const int aCol = (lid >> 4) << 3;             // + ks*16
    const int bRow = wn * 64 + (lid & 7);         // + nt*8
    const int bCol = (lid & 8);                   // 0 or 8, + ks*16

    float cfr[2][8][4];
#pragma unroll
    for (int mt = 0; mt < 2; mt++)
#pragma unroll
        for (int nt = 0; nt < 8; nt++)
#pragma unroll
            for (int q = 0; q < 4; q++) cfr[mt][nt][q] = 0.0f;

    copy_chunk(0, 0);

    for (int ch = 0; ch < NCH; ch++) {
        if (ch + 1 < NCH) { copy_chunk(ch + 1, (ch + 1) & 1); CP_WAIT(1); }
        else             { CP_WAIT(0); }
        __syncthreads();

        const uint32_t buf = sb + (uint32_t)((ch & 1) * BUFB);
#pragma unroll
        for (int ks = 0; ks < 2; ks++) {
            const int kcol = ks * 16;
            uint32_t ah[2][4], al[2][4], bb[8][2];
            // Ahi frags
#pragma unroll
            for (int mt = 0; mt < 2; mt++)
                ldsm_x4(ah[mt], buf + (uint32_t)((aRow + mt * 16) * ROWB
                                                 + (kcol + aCol) * 2));
            // Bhi frags
#pragma unroll
            for (int nt = 0; nt < 8; nt++)
                ldsm_x2(bb[nt], buf + (uint32_t)(2 * MATB
                                                 + (bRow + nt * 8) * ROWB
                                                 + (kcol + bCol) * 2));
            // T1: Ah * Bh
#pragma unroll
            for (int mt = 0; mt < 2; mt++)
#pragma unroll
                for (int nt = 0; nt < 8; nt++)
                    mma16816(cfr[mt][nt], ah[mt], bb[nt]);
            // Alo frags, T3: Al * Bh
#pragma unroll
            for (int mt = 0; mt < 2; mt++)
                ldsm_x4(al[mt], buf + (uint32_t)(MATB + (aRow + mt * 16) * ROWB
                                                 + (kcol + aCol) * 2));
#pragma unroll
            for (int mt = 0; mt < 2; mt++)
#pragma unroll
                for (int nt = 0; nt < 8; nt++)
                    mma16816(cfr[mt][nt], al[mt], bb[nt]);
            // Blo frags (reuse bb), T2: Ah * Bl
#pragma unroll
            for (int nt = 0; nt < 8; nt++)
                ldsm_x2(bb[nt], buf + (uint32_t)(3 * MATB
                                                 + (bRow + nt * 8) * ROWB
                                                 + (kcol + bCol) * 2));
#pragma unroll
            for (int mt = 0; mt < 2; mt++)
#pragma unroll
                for (int nt = 0; nt < 8; nt++)
                    mma16816(cfr[mt][nt], ah[mt], bb[nt]);
        }
        __syncthreads();
    }

    // Epilogue: bias + fp32 store
    const float* sBias = (const float*)(smem + SM_BIAS);
    const int g2 = lid >> 2;
    const int t2 = (lid & 3) * 2;
#pragma unroll
    for (int mt = 0; mt < 2; mt++) {
        const int m = mb * 128 + wm * 32 + mt * 16 + g2;
#pragma unroll
        for (int nt = 0; nt < 8; nt++) {
            const int ncol = wn * 64 + nt * 8 + t2;       // within 128 block
            const float b0 = sBias[ncol], b1 = sBias[ncol + 1];
            float* cp0 = C + (size_t)m * HIDDEN + nb * 128 + ncol;
            float* cp1 = cp0 + 8 * HIDDEN;
            float2 v0 = {cfr[mt][nt][0] + b0, cfr[mt][nt][1] + b1};
            float2 v1 = {cfr[mt][nt][2] + b0, cfr[mt][nt][3] + b1};
            *(float2*)cp0 = v0;
            *(float2*)cp1 = v1;
        }
    }
}

// ---------------------------------------------------------------------------
// Phase 2: scan with MUFU-based sigmoid/tanh. One thread per (b, j).
// tanh(x) = 1 - 2/(1+e^{2x}) (saturates correctly at +/-inf).
// ---------------------------------------------------------------------------
__global__ __launch_bounds__(128)
void brc_scan(float* __restrict__ out, const float* __restrict__ h0,
              const float* __restrict__ w_c, const float* __restrict__ w_a,
              float* __restrict__ hn) {
    const int tid = blockIdx.x * 128 + threadIdx.x;     // 0..65535
    const int j = tid & (HIDDEN - 1);
    const float wc = w_c[j];
    const float wa = w_a[j];
    float h = h0[tid];
    const int STRIDE = BATCH * HIDDEN;

    float xct = g_xc[tid];
    float xat = g_xa[tid];
    float xht = out[tid];

    size_t idx = (size_t)tid;
    for (int t = 0; t < SEQ; ++t, idx += STRIDE) {
        const float xc_c = xct, xa_c = xat, xh_c = xht;
        if (t + 1 < SEQ) {
            xct = g_xc[idx + STRIDE];
            xat = g_xa[idx + STRIDE];
            xht = out[idx + STRIDE];
        }
        const float c  = __fdividef(1.0f, 1.0f + __expf(-(xc_c + wc * h)));
        const float ra = __fdividef(1.0f, 1.0f + __expf(2.0f * (xa_c + wa * h)));
        const float a  = fmaf(-2.0f, ra, 2.0f);          // 1 + tanh
        const float rh = __fdividef(1.0f, 1.0f + __expf(2.0f * (xh_c + a * h)));
        const float t3 = fmaf(-2.0f, rh, 1.0f);          // tanh
        h = fmaf(c, h - t3, t3);
        out[idx] = h;
    }
    if (hn) hn[tid] = h;
}

// ---------------------------------------------------------------------------
extern "C" void kernel_launch(void* const* d_in, const int* in_sizes, int n_in,
                              void* d_out, int out_size) {
    const float* x  = (const float*)d_in[0];
    const float* h0 = (const float*)d_in[1];
    const float* Uc = (const float*)d_in[2];
    const float* wc = (const float*)d_in[3];
    const float* bc = (const float*)d_in[4];
    const float* Ua = (const float*)d_in[5];
    const float* wa = (const float*)d_in[6];
    const float* ba = (const float*)d_in[7];
    const float* Uh = (const float*)d_in[8];

    float* out = (float*)d_out;
    const size_t out_elems = (size_t)SEQ * BATCH * HIDDEN;
    float* hn = ((size_t)out_size >= out_elems + (size_t)BATCH * HIDDEN)
                    ? (out + out_elems) : nullptr;

    // Pre-pass: fp32 -> bf16 hi/lo splits
    splitA<<<(MDIM * INPUT / 8) / 256, 256>>>(x);
    splitB<<<(HIDDEN * INPUT / 8) / 256, 256>>>(Uc, 0);
    splitB<<<(HIDDEN * INPUT / 8) / 256, 256>>>(Ua, 1);
    splitB<<<(HIDDEN * INPUT / 8) / 256, 256>>>(Uh, 2);

    // Phase 1: mma.sync GEMMs (xc -> g_xc, xa -> g_xa, xh -> d_out region)
    static int smem_set = 0;
    if (!smem_set) {
        cudaFuncSetAttribute(brc_gemm_mma,
                             cudaFuncAttributeMaxDynamicSharedMemorySize,
                             SMEM_TOT);
        smem_set = 1;
    }
    dim3 grid(12, MDIM / 128);
    brc_gemm_mma<<<grid, 256, SMEM_TOT>>>(bc, ba, out);

    // Phase 2: recurrent scan, in place over xh
    brc_scan<<<(BATCH * HIDDEN) / 128, 128>>>(out, h0, wc, wa, hn);
}

// round 5
// speedup vs baseline: 2.7276x; 1.1402x over previous
#include <cuda_runtime.h>
#include <cuda_bf16.h>
#include <cstdint>
#include <cstddef>

#define SEQ    2048
#define BATCH  128
#define INPUT  256
#define HIDDEN 512
#define MDIM   (SEQ * BATCH)          // 262144 GEMM rows

// ---------------------------------------------------------------------------
// Device scratch (no allocations allowed)
// ---------------------------------------------------------------------------
__device__ float g_xc[(size_t)SEQ * BATCH * HIDDEN];
__device__ float g_xa[(size_t)SEQ * BATCH * HIDDEN];
__device__ __nv_bfloat16 g_Ahi[(size_t)MDIM * INPUT];
__device__ __nv_bfloat16 g_Alo[(size_t)MDIM * INPUT];
__device__ __nv_bfloat16 g_Bhi[3 * HIDDEN * INPUT];
__device__ __nv_bfloat16 g_Blo[3 * HIDDEN * INPUT];

// ---------------------------------------------------------------------------
// PTX helpers (plain sm_80-level PTX; assembles for compute_103)
// ---------------------------------------------------------------------------
__device__ __forceinline__ uint32_t smem_to_u32(const void* p) {
    uint32_t a;
    asm("{ .reg .u64 t; cvta.to.shared.u64 t, %1; cvt.u32.u64 %0, t; }"
        : "=r"(a) : "l"(p));
    return a;
}
__device__ __forceinline__ void cp16(uint32_t dst, const void* src) {
    asm volatile("cp.async.cg.shared.global [%0], [%1], 16;"
                 :: "r"(dst), "l"(src));
}
#define CP_COMMIT() asm volatile("cp.async.commit_group;" ::: "memory")
#define CP_WAIT(n)  asm volatile("cp.async.wait_group %0;" :: "n"(n) : "memory")

__device__ __forceinline__ void ldsm_x4(uint32_t* r, uint32_t addr) {
    asm volatile("ldmatrix.sync.aligned.m8n8.x4.shared.b16 {%0,%1,%2,%3}, [%4];"
                 : "=r"(r[0]), "=r"(r[1]), "=r"(r[2]), "=r"(r[3]) : "r"(addr));
}
__device__ __forceinline__ void mma16816(float* c, const uint32_t* a,
                                         const uint32_t* b) {
    asm volatile(
        "mma.sync.aligned.m16n8k16.row.col.f32.bf16.bf16.f32 "
        "{%0,%1,%2,%3}, {%4,%5,%6,%7}, {%8,%9}, {%0,%1,%2,%3};"
        : "+f"(c[0]), "+f"(c[1]), "+f"(c[2]), "+f"(c[3])
        : "r"(a[0]), "r"(a[1]), "r"(a[2]), "r"(a[3]), "r"(b[0]), "r"(b[1]));
}
__device__ __forceinline__ uint32_t sw128(uint32_t off) {
    return off ^ ((off >> 3) & 0x70);
}

// ---------------------------------------------------------------------------
// Pre-pass: split fp32 -> bf16 hi/lo
// ---------------------------------------------------------------------------
__global__ void splitA(const float* __restrict__ x) {
    const size_t base = ((size_t)blockIdx.x * blockDim.x + threadIdx.x) * 8;
    float4 a = *(const float4*)(x + base);
    float4 b = *(const float4*)(x + base + 4);
    float f[8] = {a.x, a.y, a.z, a.w, b.x, b.y, b.z, b.w};
    union { __nv_bfloat16 h[8]; uint4 u; } H, L;
#pragma unroll
    for (int k = 0; k < 8; k++) {
        H.h[k] = __float2bfloat16_rn(f[k]);
        L.h[k] = __float2bfloat16_rn(f[k] - __bfloat162float(H.h[k]));
    }
    *(uint4*)(g_Ahi + base) = H.u;
    *(uint4*)(g_Alo + base) = L.u;
}
__global__ void splitB3(const float* __restrict__ Uc,
                        const float* __restrict__ Ua,
                        const float* __restrict__ Uh) {
    const int proj = blockIdx.y;
    const float* u = (proj == 0) ? Uc : (proj == 1) ? Ua : Uh;
    const size_t base = ((size_t)blockIdx.x * blockDim.x + threadIdx.x) * 8;
    const size_t off = (size_t)proj * HIDDEN * INPUT;
    float4 a = *(const float4*)(u + base);
    float4 b = *(const float4*)(u + base + 4);
    float f[8] = {a.x, a.y, a.z, a.w, b.x, b.y, b.z, b.w};
    union { __nv_bfloat16 h[8]; uint4 u4; } H, L;
#pragma unroll
    for (int k = 0; k < 8; k++) {
        H.h[k] = __float2bfloat16_rn(f[k]);
        L.h[k] = __float2bfloat16_rn(f[k] - __bfloat162float(H.h[k]));
    }
    *(uint4*)(g_Bhi + off + base) = H.u4;
    *(uint4*)(g_Blo + off + base) = L.u4;
}

// ---------------------------------------------------------------------------
// Persistent-B mma.sync GEMM. grid = (12, 256), block = 256 (8 warps).
// Each CTA: fixed (proj, nb) -> B hi/lo 128x256 resident in SMEM (128 KB),
// sweeps 8 M-tiles, streaming A hi/lo in K-chunks of 64 (32 KB/stage, 2
// stages). 3 split terms: Ah*Bh + Al*Bh + Ah*Bl. fp32 accumulate.
// SMEM tiles: 128 rows x 128 B (K=64 bf16), SW128 XOR swizzle.
// Epilogue: fp32 (+bias) everywhere.
// ---------------------------------------------------------------------------
#define MATB     16384                 // 128 x 128 B
#define SM_B     0                     // 8 mats: (kc*2+hl)*MATB, kc 0..3
#define SM_A     (8 * MATB)            // 2 stages x {hi, lo}
#define SM_BIAS  (8 * MATB + 4 * MATB) // 196608
#define SMEM_TOT (SM_BIAS + 512)       // 197120 bytes
#define TILES    8

__global__ __launch_bounds__(256, 1)
void brc_gemm_pb(const float* __restrict__ bc, const float* __restrict__ ba,
                 float* __restrict__ xh_out) {
    extern __shared__ __align__(1024) char smem[];
    const uint32_t sb = smem_to_u32(smem);
    const int tid = threadIdx.x;
    const int wid = tid >> 5;
    const int lid = tid & 31;

    const int colblk = blockIdx.x;     // 0..11
    const int proj   = colblk >> 2;
    const int nb     = colblk & 3;
    const int yb     = blockIdx.y;     // 0..255

    float* __restrict__ C = (proj == 0) ? g_xc : (proj == 1) ? g_xa : xh_out;

    // bias -> smem (zero for proj 2)
    if (tid < 128) {
        float bv = 0.0f;
        if (proj == 0) bv = bc[nb * 128 + tid];
        else if (proj == 1) bv = ba[nb * 128 + tid];
        ((float*)(smem + SM_BIAS))[tid] = bv;
    }

    // ---- B preload: 8 mats (4 kc x hi/lo), 32 cp.async per thread ----
    {
        const __nv_bfloat16* Bh = g_Bhi + (size_t)proj * HIDDEN * INPUT
                                        + (size_t)(nb * 128) * INPUT;
        const __nv_bfloat16* Bl = g_Blo + (size_t)proj * HIDDEN * INPUT
                                        + (size_t)(nb * 128) * INPUT;
#pragma unroll
        for (int i = 0; i < 32; i++) {
            const int kcmat = i >> 2;              // 0..7
            const int kc = kcmat >> 1, hl = kcmat & 1;
            const int within = ((i & 3) << 8) + tid;   // 0..1023
            const int r = within >> 3, s = within & 7;
            const __nv_bfloat16* g = ((hl == 0) ? Bh : Bl)
                                     + (size_t)r * INPUT + kc * 64 + s * 8;
            cp16(sb + (uint32_t)(SM_B + kcmat * MATB + sw128(r * 128 + s * 16)), g);
        }
        CP_COMMIT();
    }

    // A chunk copy: chunk index q (0..31): tile t = q>>2, kc = q&3
    auto copy_A = [&](int q) {
        const int t = q >> 2, kc = q & 3;
        const size_t mrow = (size_t)(yb * 8 + t) * 128;
        const uint32_t stage = sb + (uint32_t)(SM_A + (q & 1) * 2 * MATB);
#pragma unroll
        for (int i = 0; i < 8; i++) {
            const int hl = i >> 2;
            const int within = ((i & 3) << 8) + tid;
            const int r = within >> 3, s = within & 7;
            const __nv_bfloat16* g = ((hl == 0) ? g_Ahi : g_Alo)
                + (mrow + r) * INPUT + kc * 64 + s * 8;
            cp16(stage + (uint32_t)(hl * MATB + sw128(r * 128 + s * 16)), g);
        }
        CP_COMMIT();
    };
    copy_A(0);

    // warp layout: 4(M) x 2(N); warp tile 32 x 64
    const int wm = wid & 3;
    const int wn = wid >> 2;
    // ldmatrix lane address components (element units)
    const int aRow = wm * 32 + (lid & 15);          // + mt*16
    const int aColE = (lid >> 4) << 3;              // 0/8, + k16*16
    const int bRow = wn * 64 + (lid & 7) + ((lid >> 4) << 3);  // + pr*16
    const int bColE = ((lid >> 3) & 1) << 3;        // 0/8, + k16*16

    float cfr[2][8][4];
    const float* sBias = (const float*)(smem + SM_BIAS);

    for (int q = 0; q < TILES * 4; q++) {
        const int kc = q & 3;
        if (kc == 0) {
#pragma unroll
            for (int mt = 0; mt < 2; mt++)
#pragma unroll
                for (int nt = 0; nt < 8; nt++)
#pragma unroll
                    for (int p = 0; p < 4; p++) cfr[mt][nt][p] = 0.0f;
        }
        if (q + 1 < TILES * 4) { copy_A(q + 1); CP_WAIT(1); }
        else                   { CP_WAIT(0); }
        __syncthreads();

        const uint32_t abuf = sb + (uint32_t)(SM_A + (q & 1) * 2 * MATB);
        const uint32_t bbuf = sb + (uint32_t)(SM_B + kc * 2 * MATB);
#pragma unroll
        for (int k16 = 0; k16 < 4; k16++) {
            const int kcolb = k16 * 32;             // byte col of k16 block
            uint32_t ah[2][4], al[2][4], bb[8][2];
#pragma unroll
            for (int mt = 0; mt < 2; mt++)
                ldsm_x4(ah[mt], abuf + sw128((aRow + mt * 16) * 128
                                             + kcolb + aColE * 2));
#pragma unroll
            for (int pr = 0; pr < 4; pr++)          // B hi: 4 x4 = 8 nt
                ldsm_x4(&bb[pr * 2][0], bbuf + sw128((bRow + pr * 16) * 128
                                                     + kcolb + bColE * 2));
#pragma unroll
            for (int mt = 0; mt < 2; mt++)
#pragma unroll
                for (int nt = 0; nt < 8; nt++)
                    mma16816(cfr[mt][nt], ah[mt], bb[nt]);
#pragma unroll
            for (int mt = 0; mt < 2; mt++)          // A lo
                ldsm_x4(al[mt], abuf + (uint32_t)MATB
                                + sw128((aRow + mt * 16) * 128
                                        + kcolb + aColE * 2));
#pragma unroll
            for (int mt = 0; mt < 2; mt++)
#pragma unroll
                for (int nt = 0; nt < 8; nt++)
                    mma16816(cfr[mt][nt], al[mt], bb[nt]);
#pragma unroll
            for (int pr = 0; pr < 4; pr++)          // B lo (reuse bb)
                ldsm_x4(&bb[pr * 2][0], bbuf + (uint32_t)MATB
                                        + sw128((bRow + pr * 16) * 128
                                                + kcolb + bColE * 2));
#pragma unroll
            for (int mt = 0; mt < 2; mt++)
#pragma unroll
                for (int nt = 0; nt < 8; nt++)
                    mma16816(cfr[mt][nt], ah[mt], bb[nt]);
        }

        if (kc == 3) {      // fp32 epilogue for tile t
            const int t = q >> 2;
            const int mbase = (yb * 8 + t) * 128 + wm * 32 + (lid >> 2);
            const int t2 = (lid & 3) * 2;
#pragma unroll
            for (int mt = 0; mt < 2; mt++) {
                const size_t m0 = (size_t)(mbase + mt * 16);
#pragma unroll
                for (int nt = 0; nt < 8; nt++) {
                    const int ncol = wn * 64 + nt * 8 + t2;
                    const float b0 = sBias[ncol], b1 = sBias[ncol + 1];
                    float* p0 = C + m0 * HIDDEN + nb * 128 + ncol;
                    *(float2*)p0 = make_float2(cfr[mt][nt][0] + b0,
                                               cfr[mt][nt][1] + b1);
                    *(float2*)(p0 + 8 * HIDDEN) = make_float2(
                        cfr[mt][nt][2] + b0, cfr[mt][nt][3] + b1);
                }
            }
        }
        __syncthreads();    // protect other A stage before next copy
    }
}

// ---------------------------------------------------------------------------
// Phase 2: scan with MUFU-based sigmoid/tanh. One thread per (b, j).
// tanh(x) = 1 - 2/(1+e^{2x}) (saturates correctly at +/-inf).
// ---------------------------------------------------------------------------
__global__ __launch_bounds__(256)
void brc_scan(float* __restrict__ out, const float* __restrict__ h0,
              const float* __restrict__ w_c, const float* __restrict__ w_a,
              float* __restrict__ hn) {
    const int tid = blockIdx.x * 256 + threadIdx.x;     // 0..65535
    const int j = tid & (HIDDEN - 1);
    const float wc = w_c[j];
    const float wa = w_a[j];
    float h = h0[tid];
    const int STRIDE = BATCH * HIDDEN;

    float xct = g_xc[tid];
    float xat = g_xa[tid];
    float xht = out[tid];

    size_t idx = (size_t)tid;
    for (int t = 0; t < SEQ; ++t, idx += STRIDE) {
        const float xc_c = xct, xa_c = xat, xh_c = xht;
        if (t + 1 < SEQ) {
            xct = g_xc[idx + STRIDE];
            xat = g_xa[idx + STRIDE];
            xht = out[idx + STRIDE];
        }
        const float c  = __fdividef(1.0f, 1.0f + __expf(-(xc_c + wc * h)));
        const float ra = __fdividef(1.0f, 1.0f + __expf(2.0f * (xa_c + wa * h)));
        const float a  = fmaf(-2.0f, ra, 2.0f);          // 1 + tanh
        const float rh = __fdividef(1.0f, 1.0f + __expf(2.0f * (xh_c + a * h)));
        const float t3 = fmaf(-2.0f, rh, 1.0f);          // tanh
        h = fmaf(c, h - t3, t3);
        out[idx] = h;
    }
    if (hn) hn[tid] = h;
}

// ---------------------------------------------------------------------------
extern "C" void kernel_launch(void* const* d_in, const int* in_sizes, int n_in,
                              void* d_out, int out_size) {
    const float* x  = (const float*)d_in[0];
    const float* h0 = (const float*)d_in[1];
    const float* Uc = (const float*)d_in[2];
    const float* wc = (const float*)d_in[3];
    const float* bc = (const float*)d_in[4];
    const float* Ua = (const float*)d_in[5];
    const float* wa = (const float*)d_in[6];
    const float* ba = (const float*)d_in[7];
    const float* Uh = (const float*)d_in[8];

    float* out = (float*)d_out;
    const size_t out_elems = (size_t)SEQ * BATCH * HIDDEN;
    float* hn = ((size_t)out_size >= out_elems + (size_t)BATCH * HIDDEN)
                    ? (out + out_elems) : nullptr;

    // Pre-pass: fp32 -> bf16 hi/lo splits
    splitA<<<(MDIM * INPUT / 8) / 256, 256>>>(x);
    dim3 gb(HIDDEN * INPUT / 8 / 256, 3);
    splitB3<<<gb, 256>>>(Uc, Ua, Uh);

    // Phase 1: persistent-B mma.sync GEMMs
    cudaFuncSetAttribute(brc_gemm_pb,
                         cudaFuncAttributeMaxDynamicSharedMemorySize, SMEM_TOT);
    dim3 grid(12, 256);
    brc_gemm_pb<<<grid, 256, SMEM_TOT>>>(bc, ba, out);

    // Phase 2: recurrent scan, in place over xh
    brc_scan<<<(BATCH * HIDDEN) / 256, 256>>>(out, h0, wc, wa, hn);
}